// round 17
// baseline (speedup 1.0000x reference)
#include <cuda_runtime.h>
#include <cuda_fp16.h>
#include <cstdint>

#define NN    20000
#define EE    320000
#define E2T   340000          // EE + NN self loops
#define HIDC  256
#define NH    4
#define NEG   0.2f

// ---------------- device scratch (static, no allocation) ----------------
__device__ __align__(16) __half g_xlh[NN * HIDC];   // fp16 xl (halved attn traffic)
__device__ __align__(16) float g_xr[NN * HIDC];
__device__ __align__(16) float g_h [NN * HIDC];
__device__ int g_cnt[NN];
__device__ int g_off[NN + 1];
__device__ int g_cur[NN];
__device__ int g_srcs[E2T];
__device__ int g_ctr[2];          // dynamic node tickets, one per layer

// packed fp32 FMA
__device__ __forceinline__ void ffma2(uint64_t& d, uint64_t a, uint64_t b) {
    asm("fma.rn.f32x2 %0, %1, %2, %0;" : "+l"(d) : "l"(a), "l"(b));
}
__device__ __forceinline__ uint64_t fma2v(uint64_t a, uint64_t b, uint64_t c) {
    uint64_t d;
    asm("fma.rn.f32x2 %0, %1, %2, %3;" : "=l"(d) : "l"(a), "l"(b), "l"(c));
    return d;
}
__device__ __forceinline__ float2 unpack2(uint64_t v) {
    uint32_t lo, hi;
    asm("mov.b64 {%0, %1}, %2;" : "=r"(lo), "=r"(hi) : "l"(v));
    return make_float2(__uint_as_float(lo), __uint_as_float(hi));
}
__device__ __forceinline__ uint64_t pack2(float x) {
    uint64_t d;
    asm("mov.b64 %0, {%1, %1};" : "=l"(d) : "r"(__float_as_uint(x)));
    return d;
}
__device__ __forceinline__ uint64_t pack2f(float2 v) {
    uint64_t d;
    asm("mov.b64 %0, {%1, %2};" : "=l"(d) : "r"(__float_as_uint(v.x)), "r"(__float_as_uint(v.y)));
    return d;
}
#define C_ONE2  0x3F8000003F800000ull   // (1.0f, 1.0f)
#define C_06    0x3F19999A3F19999Aull   // (0.6f, 0.6f)
#define C_04    0x3ECCCCCD3ECCCCCDull   // (0.4f, 0.4f)
#define C_ABS   0x7FFFFFFF7FFFFFFFull

// ---------------- fused dual GEMM (xl fp16 & xr fp32), fma.rn.f32x2 -----------
// CTA tile 96(M) x 128(N), 256 threads, 6x8 outputs/thread.
__global__ void __launch_bounds__(256, 2)
gemm_dual(const float* __restrict__ Ain, int a_is_gh,
          const float* __restrict__ Wl, const float* __restrict__ bl,
          const float* __restrict__ Wr, const float* __restrict__ br) {
    __shared__ float As[16][100];   // [k][m] 96 + pad 4
    __shared__ float Bs[16][136];   // [k][n] 128 + pad 8

    const float* A = a_is_gh ? g_h : Ain;
    int by = blockIdx.y;
    int sel = by >> 1;
    const float* W    = sel ? Wr : Wl;
    const float* bias = sel ? br : bl;
    int bn = (by & 1) * 128;
    int bm = blockIdx.x * 96;

    int tid = threadIdx.x;
    int tx = tid & 15, ty = tid >> 4;
    bool aload = tid < 192;
    int e0 = tid * 2, e1 = tid * 2 + 1;
    int r0 = e0 >> 2, q0 = e0 & 3;
    int r1 = e1 >> 2, q1 = e1 & 3;
    int w_r = tid >> 4, w_c = tid & 15;

    uint64_t acc[6][4];
    #pragma unroll
    for (int i = 0; i < 6; i++)
        #pragma unroll
        for (int q = 0; q < 4; q++) acc[i][q] = 0ull;

    float4 pa0 = make_float4(0.f, 0.f, 0.f, 0.f);
    float4 pa1 = make_float4(0.f, 0.f, 0.f, 0.f);
    float4 pb[2];
    if (aload) {
        if (bm + r0 < NN) pa0 = *(const float4*)(A + (size_t)(bm + r0) * 256 + q0 * 4);
        if (bm + r1 < NN) pa1 = *(const float4*)(A + (size_t)(bm + r1) * 256 + q1 * 4);
    }
    #pragma unroll
    for (int h = 0; h < 2; h++)
        pb[h] = *(const float4*)(W + (size_t)w_r * 256 + bn + h * 64 + w_c * 4);

    for (int k0 = 0; k0 < 256; k0 += 16) {
        if (aload) {
            As[q0 * 4 + 0][r0] = pa0.x;
            As[q0 * 4 + 1][r0] = pa0.y;
            As[q0 * 4 + 2][r0] = pa0.z;
            As[q0 * 4 + 3][r0] = pa0.w;
            As[q1 * 4 + 0][r1] = pa1.x;
            As[q1 * 4 + 1][r1] = pa1.y;
            As[q1 * 4 + 2][r1] = pa1.z;
            As[q1 * 4 + 3][r1] = pa1.w;
        }
        #pragma unroll
        for (int h = 0; h < 2; h++)
            *(float4*)&Bs[w_r][h * 64 + w_c * 4] = pb[h];
        __syncthreads();

        if (k0 < 240) {
            int kn = k0 + 16;
            if (aload) {
                if (bm + r0 < NN)
                    pa0 = *(const float4*)(A + (size_t)(bm + r0) * 256 + kn + q0 * 4);
                if (bm + r1 < NN)
                    pa1 = *(const float4*)(A + (size_t)(bm + r1) * 256 + kn + q1 * 4);
            }
            #pragma unroll
            for (int h = 0; h < 2; h++)
                pb[h] = *(const float4*)(W + (size_t)(kn + w_r) * 256 + bn + h * 64 + w_c * 4);
        }

        #pragma unroll
        for (int k = 0; k < 16; k++) {
            float2 af0 = *(const float2*)&As[k][ty * 6];
            float2 af1 = *(const float2*)&As[k][ty * 6 + 2];
            float2 af2 = *(const float2*)&As[k][ty * 6 + 4];
            ulonglong2 u = *(const ulonglong2*)&Bs[k][tx * 4];
            ulonglong2 v = *(const ulonglong2*)&Bs[k][64 + tx * 4];
            uint64_t ar[6];
            ar[0] = pack2(af0.x); ar[1] = pack2(af0.y);
            ar[2] = pack2(af1.x); ar[3] = pack2(af1.y);
            ar[4] = pack2(af2.x); ar[5] = pack2(af2.y);
            #pragma unroll
            for (int i = 0; i < 6; i++) {
                ffma2(acc[i][0], ar[i], u.x);
                ffma2(acc[i][1], ar[i], u.y);
                ffma2(acc[i][2], ar[i], v.x);
                ffma2(acc[i][3], ar[i], v.y);
            }
        }
        __syncthreads();
    }

    float4 bv0 = *(const float4*)(bias + bn + tx * 4);
    float4 bv1 = *(const float4*)(bias + bn + 64 + tx * 4);
    #pragma unroll
    for (int i = 0; i < 6; i++) {
        int row = bm + ty * 6 + i;
        if (row < NN) {
            float2 c0 = unpack2(acc[i][0]), c1 = unpack2(acc[i][1]);
            float2 c2 = unpack2(acc[i][2]), c3 = unpack2(acc[i][3]);
            float4 o0 = make_float4(c0.x + bv0.x, c0.y + bv0.y, c1.x + bv0.z, c1.y + bv0.w);
            float4 o1 = make_float4(c2.x + bv1.x, c2.y + bv1.y, c3.x + bv1.z, c3.y + bv1.w);
            if (sel == 0) {
                // xl -> fp16
                __half2 h01 = __floats2half2_rn(o0.x, o0.y);
                __half2 h23 = __floats2half2_rn(o0.z, o0.w);
                __half2 h45 = __floats2half2_rn(o1.x, o1.y);
                __half2 h67 = __floats2half2_rn(o1.z, o1.w);
                *(uint2*)(g_xlh + (size_t)row * 256 + bn + tx * 4) =
                    make_uint2(*(uint32_t*)&h01, *(uint32_t*)&h23);
                *(uint2*)(g_xlh + (size_t)row * 256 + bn + 64 + tx * 4) =
                    make_uint2(*(uint32_t*)&h45, *(uint32_t*)&h67);
            } else {
                *(float4*)(g_xr + (size_t)row * 256 + bn + tx * 4) = o0;
                *(float4*)(g_xr + (size_t)row * 256 + bn + 64 + tx * 4) = o1;
            }
        }
    }
}

// ---------------- CSR build (once per launch; edges shared by both layers) ----
__global__ void hist_init_k() {
    int i = blockIdx.x * blockDim.x + threadIdx.x;
    if (i < NN) g_cnt[i] = 1;      // self loop pre-counted
    if (i < 2)  g_ctr[i] = 0;
}
__global__ void hist_k(const int* __restrict__ ei) {
    int e = blockIdx.x * blockDim.x + threadIdx.x;
    if (e < EE) atomicAdd(&g_cnt[ei[EE + e]], 1);
}
__global__ void scan_k() {
    __shared__ int sums[1024];
    int t = threadIdx.x;
    int base = t * 20;
    int s = 0;
    if (t < 1000) {
        #pragma unroll
        for (int i = 0; i < 20; i++) s += g_cnt[base + i];
    }
    sums[t] = s;
    __syncthreads();
    #pragma unroll
    for (int d = 1; d < 1024; d <<= 1) {
        int v = (t >= d) ? sums[t - d] : 0;
        __syncthreads();
        sums[t] += v;
        __syncthreads();
    }
    if (t < 1000) {
        int run = (t == 0) ? 0 : sums[t - 1];
        #pragma unroll
        for (int i = 0; i < 20; i++) {
            g_off[base + i] = run;
            g_cur[base + i] = run;
            run += g_cnt[base + i];
        }
        if (t == 999) g_off[NN] = run;
    }
}
__global__ void scatter_k(const int* __restrict__ ei) {
    int e = blockIdx.x * blockDim.x + threadIdx.x;
    if (e >= E2T) return;
    int src, dst;
    if (e < EE) { src = ei[e]; dst = ei[EE + e]; }
    else        { src = e - EE; dst = src; }
    int pos = atomicAdd(&g_cur[dst], 1);
    g_srcs[pos] = src;
}

// ---------------- packed-f32x2 attention core (fp16 xl, 4-edge groups) --------
__device__ __forceinline__ float edge_logit(const uint64_t* tp, const uint64_t* rp,
                                            const uint64_t* lp) {
    uint64_t s2 = 0ull;
    #pragma unroll
    for (int i = 0; i < 4; i++) {
        uint64_t u = fma2v(lp[i], C_ONE2, rp[i]);         // xl + xr
        uint64_t au = u & C_ABS;                           // |u| (alu pipe)
        uint64_t w = fma2v(au, C_04, 0ull);                // 0.4|u|
        w = fma2v(u, C_06, w);                             // 0.6u + 0.4|u|
        ffma2(s2, tp[i], w);                               // att * lrelu
    }
    float2 sv = unpack2(s2);
    return sv.x + sv.y;
}

// one uint4 load = 8 halfs = this lane's 8 channels; convert to 4 packed f32x2
__device__ __forceinline__ void load_row_h(int src, int c0, uint64_t* lp) {
    uint4 v = *(const uint4*)(g_xlh + (size_t)src * HIDC + c0);
    lp[0] = pack2f(__half22float2(*(const __half2*)&v.x));
    lp[1] = pack2f(__half22float2(*(const __half2*)&v.y));
    lp[2] = pack2f(__half22float2(*(const __half2*)&v.z));
    lp[3] = pack2f(__half22float2(*(const __half2*)&v.w));
}

__global__ void __launch_bounds__(256)
attn_fused_k(const float* __restrict__ att, const float* __restrict__ bias,
             float* __restrict__ dout, int to_gh, int lsel) {
    int lane = threadIdx.x & 31;
    int c0 = lane * 8;
    int head = lane >> 3;

    uint64_t tp[4];
    {
        const ulonglong2* a2 = (const ulonglong2*)(att + head * 64 + (lane & 7) * 8);
        ulonglong2 u0 = a2[0], u1 = a2[1];
        tp[0] = u0.x; tp[1] = u0.y; tp[2] = u1.x; tp[3] = u1.y;
    }
    const float4* b4 = (const float4*)(bias + c0);
    float4 b0 = b4[0], b1 = b4[1];
    float* obase = to_gh ? g_h : dout;

    int n;
    if (lane == 0) n = atomicAdd(&g_ctr[lsel], 1);
    n = __shfl_sync(0xffffffffu, n, 0);

    while (n < NN) {
        int nn;
        if (lane == 0) nn = atomicAdd(&g_ctr[lsel], 1);   // prefetch next ticket

        uint64_t rp[4];
        {
            const ulonglong2* r2 = (const ulonglong2*)(g_xr + (size_t)n * HIDC + c0);
            ulonglong2 u0 = r2[0], u1 = r2[1];
            rp[0] = u0.x; rp[1] = u0.y; rp[2] = u1.x; rp[3] = u1.y;
        }

        uint64_t acc[4] = {0ull, 0ull, 0ull, 0ull};
        float den = 0.f;

        int jb = g_off[n], je = g_off[n + 1];
        for (int base = jb; base < je; base += 32) {
            int rem = je - base;
            int cnt = rem < 32 ? rem : 32;
            int midx = 0;
            if (base + lane < je) midx = g_srcs[base + lane];

            int j = 0;
            for (; j + 3 < cnt; j += 4) {
                int sa = __shfl_sync(0xffffffffu, midx, j);
                int sb = __shfl_sync(0xffffffffu, midx, j + 1);
                int sc = __shfl_sync(0xffffffffu, midx, j + 2);
                int sd = __shfl_sync(0xffffffffu, midx, j + 3);
                uint64_t lpa[4], lpb[4], lpc[4], lpd[4];
                load_row_h(sa, c0, lpa);
                load_row_h(sb, c0, lpb);
                load_row_h(sc, c0, lpc);
                load_row_h(sd, c0, lpd);

                float s0 = edge_logit(tp, rp, lpa);
                float s1 = edge_logit(tp, rp, lpb);
                float s2 = edge_logit(tp, rp, lpc);
                float s3 = edge_logit(tp, rp, lpd);

                s0 += __shfl_xor_sync(0xffffffffu, s0, 1);
                s1 += __shfl_xor_sync(0xffffffffu, s1, 1);
                s2 += __shfl_xor_sync(0xffffffffu, s2, 1);
                s3 += __shfl_xor_sync(0xffffffffu, s3, 1);
                s0 += __shfl_xor_sync(0xffffffffu, s0, 2);
                s1 += __shfl_xor_sync(0xffffffffu, s1, 2);
                s2 += __shfl_xor_sync(0xffffffffu, s2, 2);
                s3 += __shfl_xor_sync(0xffffffffu, s3, 2);
                s0 += __shfl_xor_sync(0xffffffffu, s0, 4);
                s1 += __shfl_xor_sync(0xffffffffu, s1, 4);
                s2 += __shfl_xor_sync(0xffffffffu, s2, 4);
                s3 += __shfl_xor_sync(0xffffffffu, s3, 4);

                float e0 = __expf(s0), e1 = __expf(s1);
                float e2 = __expf(s2), e3 = __expf(s3);
                den += (e0 + e1) + (e2 + e3);
                uint64_t e02 = pack2(e0), e12 = pack2(e1);
                uint64_t e22 = pack2(e2), e32 = pack2(e3);
                #pragma unroll
                for (int q = 0; q < 4; q++) {
                    ffma2(acc[q], e02, lpa[q]);
                    ffma2(acc[q], e12, lpb[q]);
                    ffma2(acc[q], e22, lpc[q]);
                    ffma2(acc[q], e32, lpd[q]);
                }
            }
            for (; j < cnt; j++) {
                int sa = __shfl_sync(0xffffffffu, midx, j);
                uint64_t lpa[4];
                load_row_h(sa, c0, lpa);
                float s0 = edge_logit(tp, rp, lpa);
                s0 += __shfl_xor_sync(0xffffffffu, s0, 1);
                s0 += __shfl_xor_sync(0xffffffffu, s0, 2);
                s0 += __shfl_xor_sync(0xffffffffu, s0, 4);
                float e0 = __expf(s0);
                den += e0;
                uint64_t e02 = pack2(e0);
                #pragma unroll
                for (int q = 0; q < 4; q++) ffma2(acc[q], e02, lpa[q]);
            }
        }

        float rd = 1.f / den;
        float2 a0 = unpack2(acc[0]), a1 = unpack2(acc[1]);
        float2 a2 = unpack2(acc[2]), a3 = unpack2(acc[3]);
        float4 o0, o1;
        o0.x = fmaxf(a0.x * rd + b0.x, 0.f);
        o0.y = fmaxf(a0.y * rd + b0.y, 0.f);
        o0.z = fmaxf(a1.x * rd + b0.z, 0.f);
        o0.w = fmaxf(a1.y * rd + b0.w, 0.f);
        o1.x = fmaxf(a2.x * rd + b1.x, 0.f);
        o1.y = fmaxf(a2.y * rd + b1.y, 0.f);
        o1.z = fmaxf(a3.x * rd + b1.z, 0.f);
        o1.w = fmaxf(a3.y * rd + b1.w, 0.f);

        float4* outp = (float4*)(obase + (size_t)n * HIDC + c0);
        outp[0] = o0;
        outp[1] = o1;

        n = __shfl_sync(0xffffffffu, nn, 0);
    }
}

// ---------------- host ----------------
extern "C" void kernel_launch(void* const* d_in, const int* in_sizes, int n_in,
                              void* d_out, int out_size) {
    const float* x     = (const float*)d_in[0];
    const int*   ei    = (const int*)  d_in[1];
    const float* Wl1   = (const float*)d_in[2];
    const float* bl1   = (const float*)d_in[3];
    const float* Wr1   = (const float*)d_in[4];
    const float* br1   = (const float*)d_in[5];
    const float* att1  = (const float*)d_in[6];
    const float* bias1 = (const float*)d_in[7];
    const float* Wl2   = (const float*)d_in[8];
    const float* bl2   = (const float*)d_in[9];
    const float* Wr2   = (const float*)d_in[10];
    const float* br2   = (const float*)d_in[11];
    const float* att2  = (const float*)d_in[12];
    const float* bias2 = (const float*)d_in[13];
    float* out = (float*)d_out;

    const int TB = 256;
    dim3 gg((NN + 95) / 96, 4);                   // 209 x 4 = 836 blocks
    const int awb = 148 * 4;

    // Fork a side stream: CSR build runs concurrently with layer-1 GEMM.
    cudaStream_t s2;
    cudaStreamCreateWithFlags(&s2, cudaStreamNonBlocking);
    cudaEvent_t evFork, evJoin;
    cudaEventCreateWithFlags(&evFork, cudaEventDisableTiming);
    cudaEventCreateWithFlags(&evJoin, cudaEventDisableTiming);

    cudaEventRecord(evFork, 0);
    cudaStreamWaitEvent(s2, evFork, 0);

    hist_init_k<<<(NN + TB - 1) / TB, TB, 0, s2>>>();
    hist_k<<<(EE + TB - 1) / TB, TB, 0, s2>>>(ei);
    scan_k<<<1, 1024, 0, s2>>>();
    scatter_k<<<(E2T + TB - 1) / TB, TB, 0, s2>>>(ei);
    cudaEventRecord(evJoin, s2);

    gemm_dual<<<gg, TB>>>(x, 0, Wl1, bl1, Wr1, br1);

    cudaStreamWaitEvent(0, evJoin, 0);
    attn_fused_k<<<awb, TB>>>(att1, bias1, out, 1, 0);

    gemm_dual<<<gg, TB>>>(x, 1, Wl2, bl2, Wr2, br2);
    attn_fused_k<<<awb, TB>>>(att2, bias2, out, 0, 1);
}